// round 4
// baseline (speedup 1.0000x reference)
#include <cuda_runtime.h>
#include <math.h>
#include <stdint.h>

#define NN 50000
#define EE 800000
#define HD 128
#define GG 64

// ---------------- scratch (device globals: allocation-free) ----------------
__device__ float g_z[NN * HD];
__device__ float g_h[NN * HD];
__device__ float g_dinv[NN];
__device__ int   g_degi[NN];
__device__ int   g_rowptr[NN + 1];
__device__ int   g_cursor[NN];
__device__ int   g_col[EE];
__device__ int   g_bsum[64];
__device__ float g_f[GG * HD];
__device__ float g_t1[GG * 1024];
__device__ float g_t2[GG * 512];
__device__ float g_t3[GG * 256];
__device__ float g_t4[GG * HD];

// ---------------- packed f32x2 FMA ----------------
#define FFMA2(d, a, b) \
    asm("fma.rn.f32x2 %0, %1, %2, %0;" : "+l"(d) : "l"(a), "l"(b))

// ---------------- CSR build ----------------
__global__ void k_count(const int* __restrict__ ei) {
    int e = blockIdx.x * blockDim.x + threadIdx.x;
    if (e < EE) atomicAdd(&g_degi[ei[EE + e]], 1);
}
__global__ void k_scan1() {
    __shared__ int s[1024];
    int t = threadIdx.x;
    int i = blockIdx.x * 1024 + t;
    int v = (i < NN) ? g_degi[i] : 0;
    s[t] = v;
    __syncthreads();
    for (int off = 1; off < 1024; off <<= 1) {
        int x = (t >= off) ? s[t - off] : 0;
        __syncthreads();
        s[t] += x;
        __syncthreads();
    }
    if (i < NN) g_rowptr[i] = s[t] - v;
    if (t == 1023) g_bsum[blockIdx.x] = s[1023];
}
__global__ void k_scan2(int nb) {
    __shared__ int s[64];
    int t = threadIdx.x;
    int v = (t < nb) ? g_bsum[t] : 0;
    s[t] = v;
    __syncthreads();
    for (int off = 1; off < 64; off <<= 1) {
        int x = (t >= off) ? s[t - off] : 0;
        __syncthreads();
        s[t] += x;
        __syncthreads();
    }
    if (t < nb) g_bsum[t] = s[t] - v;
}
__global__ void k_scan3() {
    int i = blockIdx.x * 1024 + threadIdx.x;
    if (i < NN) {
        int rp = g_rowptr[i] + g_bsum[blockIdx.x];
        g_rowptr[i] = rp;
        g_cursor[i] = rp;
        g_dinv[i]   = rsqrtf((float)(g_degi[i] + 1));
    }
    if (i == 0) g_rowptr[NN] = EE;
}
__global__ void k_fill(const int* __restrict__ ei) {
    int e = blockIdx.x * blockDim.x + threadIdx.x;
    if (e < EE) {
        int src = ei[e];
        int dst = ei[EE + e];
        int p = atomicAdd(&g_cursor[dst], 1);
        g_col[p] = src;
    }
}

// ---------------- FFMA2 SGEMM: C[r][c] = dinv[r] * (A @ W)[r][c] ----------
// A: [M,128], W: [128,128] (K-major), C: [M,128]
// Block 128x128, 256 threads, 8x8 per thread, BK=32.
// As2: transposed + duplicated pairs (a,a) as ull, pitch A2P (even, 16B-aligned rows)
#define BK 32
#define A2P 130
#define SM_A_ULL (BK * A2P)                      // ull count
#define SM_B_FLOATS (BK * 128)
#define SM_TOTAL_BYTES (SM_A_ULL * 8 + SM_B_FLOATS * 4)

__global__ __launch_bounds__(256, 2) void k_gemm2(const float* __restrict__ A,
                                                  const float* __restrict__ W,
                                                  float* __restrict__ C,
                                                  int M) {
    extern __shared__ char smraw[];
    unsigned long long* As2 = (unsigned long long*)smraw;
    float* Bs = (float*)(smraw + SM_A_ULL * 8);

    int tid = threadIdx.x;
    int tn  = tid & 15;          // col group: cols tn*8..tn*8+7
    int tm  = tid >> 4;          // row group: rows tm*8..tm*8+7
    int base = blockIdx.x * 128;

    unsigned long long acc[8][4];
    #pragma unroll
    for (int r = 0; r < 8; r++)
        #pragma unroll
        for (int c = 0; c < 4; c++) acc[r][c] = 0ULL;

    for (int k0 = 0; k0 < 128; k0 += BK) {
        // stage A [128 rows x 32 k] transposed + duplicated: 1024 float4 loads
        #pragma unroll
        for (int i = 0; i < 4; i++) {
            int idx = i * 256 + tid;          // 0..1023
            int row = idx >> 3;               // 0..127
            int c4  = (idx & 7) * 4;          // 0..28
            float4 a = make_float4(0.f, 0.f, 0.f, 0.f);
            int gr = base + row;
            if (gr < M) a = *(const float4*)(A + (size_t)gr * HD + k0 + c4);
            asm volatile("st.shared.v2.f32 [%0], {%1, %1};" :: "l"(&As2[(c4 + 0) * A2P + row]), "f"(a.x));
            asm volatile("st.shared.v2.f32 [%0], {%1, %1};" :: "l"(&As2[(c4 + 1) * A2P + row]), "f"(a.y));
            asm volatile("st.shared.v2.f32 [%0], {%1, %1};" :: "l"(&As2[(c4 + 2) * A2P + row]), "f"(a.z));
            asm volatile("st.shared.v2.f32 [%0], {%1, %1};" :: "l"(&As2[(c4 + 3) * A2P + row]), "f"(a.w));
        }
        // stage B [32 k x 128 n]: direct copy
        #pragma unroll
        for (int i = 0; i < 4; i++) {
            int idx = i * 256 + tid;          // 0..1023
            int k  = idx >> 5;                // 0..31
            int cl = (idx & 31) * 4;          // 0..124
            *(float4*)(Bs + k * 128 + cl) = *(const float4*)(W + (size_t)(k0 + k) * HD + cl);
        }
        __syncthreads();

        #pragma unroll
        for (int kk = 0; kk < BK; kk++) {
            unsigned long long ar[8];
            #pragma unroll
            for (int i = 0; i < 4; i++) {
                ulonglong2 v = *(const ulonglong2*)(As2 + kk * A2P + tm * 8 + 2 * i);
                ar[2 * i]     = v.x;
                ar[2 * i + 1] = v.y;
            }
            ulonglong2 b0 = *(const ulonglong2*)(Bs + kk * 128 + tn * 8);
            ulonglong2 b1 = *(const ulonglong2*)(Bs + kk * 128 + tn * 8 + 4);
            unsigned long long br[4] = {b0.x, b0.y, b1.x, b1.y};
            #pragma unroll
            for (int r = 0; r < 8; r++) {
                FFMA2(acc[r][0], ar[r], br[0]);
                FFMA2(acc[r][1], ar[r], br[1]);
                FFMA2(acc[r][2], ar[r], br[2]);
                FFMA2(acc[r][3], ar[r], br[3]);
            }
        }
        __syncthreads();
    }

    // epilogue: scale by dinv, store two float4 per row
    #pragma unroll
    for (int r = 0; r < 8; r++) {
        int row = base + tm * 8 + r;
        if (row < M) {
            float dv = g_dinv[row];
            float2 p0 = *(float2*)&acc[r][0];
            float2 p1 = *(float2*)&acc[r][1];
            float2 p2 = *(float2*)&acc[r][2];
            float2 p3 = *(float2*)&acc[r][3];
            float4 o0 = make_float4(p0.x * dv, p0.y * dv, p1.x * dv, p1.y * dv);
            float4 o1 = make_float4(p2.x * dv, p2.y * dv, p3.x * dv, p3.y * dv);
            *(float4*)(C + (size_t)row * HD + tn * 8)     = o0;
            *(float4*)(C + (size_t)row * HD + tn * 8 + 4) = o1;
        }
    }
}

// ---------------- aggregation: one warp per node ----------------
__global__ __launch_bounds__(256) void k_agg(const float* __restrict__ z,
                                             const float* __restrict__ bias,
                                             float* __restrict__ out,
                                             int relu) {
    int wid  = (blockIdx.x * blockDim.x + threadIdx.x) >> 5;
    int lane = threadIdx.x & 31;
    if (wid >= NN) return;
    const float4* z4 = (const float4*)z;
    float4 acc = z4[(size_t)wid * 32 + lane];
    int beg = g_rowptr[wid];
    int end = g_rowptr[wid + 1];
    int j = beg;
    for (; j + 3 < end; j += 4) {
        int u0 = g_col[j], u1 = g_col[j + 1], u2 = g_col[j + 2], u3 = g_col[j + 3];
        float4 a = z4[(size_t)u0 * 32 + lane];
        float4 b = z4[(size_t)u1 * 32 + lane];
        float4 c = z4[(size_t)u2 * 32 + lane];
        float4 d = z4[(size_t)u3 * 32 + lane];
        acc.x += (a.x + b.x) + (c.x + d.x);
        acc.y += (a.y + b.y) + (c.y + d.y);
        acc.z += (a.z + b.z) + (c.z + d.z);
        acc.w += (a.w + b.w) + (c.w + d.w);
    }
    for (; j < end; j++) {
        float4 a = z4[(size_t)g_col[j] * 32 + lane];
        acc.x += a.x; acc.y += a.y; acc.z += a.z; acc.w += a.w;
    }
    float dv = g_dinv[wid];
    float4 bb = ((const float4*)bias)[lane];
    float4 r;
    r.x = fmaf(acc.x, dv, bb.x);
    r.y = fmaf(acc.y, dv, bb.y);
    r.z = fmaf(acc.z, dv, bb.z);
    r.w = fmaf(acc.w, dv, bb.w);
    if (relu) {
        r.x = fmaxf(r.x, 0.f); r.y = fmaxf(r.y, 0.f);
        r.z = fmaxf(r.z, 0.f); r.w = fmaxf(r.w, 0.f);
    }
    ((float4*)out)[(size_t)wid * 32 + lane] = r;
}

// ---------------- mean pool per graph ----------------
__global__ __launch_bounds__(128) void k_pool(const float* __restrict__ h,
                                              const int* __restrict__ batch,
                                              float* __restrict__ dout) {
    int g = blockIdx.x;
    int c = threadIdx.x;
    int lo = 0, hi = NN;
    while (lo < hi) { int m = (lo + hi) >> 1; if (batch[m] < g) lo = m + 1; else hi = m; }
    int start = lo;
    lo = 0; hi = NN;
    while (lo < hi) { int m = (lo + hi) >> 1; if (batch[m] < g + 1) lo = m + 1; else hi = m; }
    int end = lo;
    float s = 0.f;
    for (int v = start; v < end; v++) s += h[(size_t)v * 128 + c];
    float cnt = (float)(end - start);
    float val = s / fmaxf(cnt, 1.0f);
    g_f[g * 128 + c] = val;
    dout[g * 128 + c] = val;
}

// ---------------- MLP layer: 64 graphs x 32-col slice per block ------------
__global__ __launch_bounds__(256) void k_fc(const float* __restrict__ in,
                                            const float* __restrict__ W,
                                            const float* __restrict__ b,
                                            float* __restrict__ out,
                                            int K, int C, int relu) {
    __shared__ float s_in[64 * 64];
    int tx = threadIdx.x & 31;
    int ty = threadIdx.x >> 5;
    int c  = blockIdx.x * 32 + tx;
    int ce = (c < C) ? c : (C - 1);
    float acc[8];
    #pragma unroll
    for (int j = 0; j < 8; j++) acc[j] = 0.f;
    for (int k0 = 0; k0 < K; k0 += 64) {
        #pragma unroll
        for (int i = 0; i < 16; i++) {
            int idx = i * 256 + threadIdx.x;
            int g = idx >> 6, k = idx & 63;
            s_in[idx] = in[(size_t)g * K + k0 + k];
        }
        __syncthreads();
        #pragma unroll 4
        for (int k = 0; k < 64; k++) {
            float w = W[(size_t)(k0 + k) * C + ce];
            #pragma unroll
            for (int j = 0; j < 8; j++)
                acc[j] = fmaf(s_in[(ty * 8 + j) * 64 + k], w, acc[j]);
        }
        __syncthreads();
    }
    if (c < C) {
        float bias = b[c];
        #pragma unroll
        for (int j = 0; j < 8; j++) {
            float v = acc[j] + bias;
            if (relu) v = fmaxf(v, 0.f);
            out[(size_t)(ty * 8 + j) * C + c] = v;
        }
    }
}

extern "C" void kernel_launch(void* const* d_in, const int* in_sizes, int n_in,
                              void* d_out, int out_size) {
    const float* x     = (const float*)d_in[0];
    const int*   ei    = (const int*)d_in[1];
    const int*   batch = (const int*)d_in[2];
    const float* c1w = (const float*)d_in[3];
    const float* c1b = (const float*)d_in[4];
    const float* c2w = (const float*)d_in[5];
    const float* c2b = (const float*)d_in[6];
    const float* c3w = (const float*)d_in[7];
    const float* c3b = (const float*)d_in[8];
    const float* f1w = (const float*)d_in[9];
    const float* f1b = (const float*)d_in[10];
    const float* f2w = (const float*)d_in[11];
    const float* f2b = (const float*)d_in[12];
    const float* f3w = (const float*)d_in[13];
    const float* f3b = (const float*)d_in[14];
    const float* f4w = (const float*)d_in[15];
    const float* f4b = (const float*)d_in[16];
    const float* f5w = (const float*)d_in[17];
    const float* f5b = (const float*)d_in[18];
    float* dout = (float*)d_out;

    float *p_z, *p_h, *p_f, *p_t1, *p_t2, *p_t3, *p_t4;
    int* p_degi;
    cudaGetSymbolAddress((void**)&p_z,  g_z);
    cudaGetSymbolAddress((void**)&p_h,  g_h);
    cudaGetSymbolAddress((void**)&p_f,  g_f);
    cudaGetSymbolAddress((void**)&p_t1, g_t1);
    cudaGetSymbolAddress((void**)&p_t2, g_t2);
    cudaGetSymbolAddress((void**)&p_t3, g_t3);
    cudaGetSymbolAddress((void**)&p_t4, g_t4);
    cudaGetSymbolAddress((void**)&p_degi, g_degi);

    static int smem_set = 0;
    if (!smem_set) {
        cudaFuncSetAttribute(k_gemm2, cudaFuncAttributeMaxDynamicSharedMemorySize, SM_TOTAL_BYTES);
        smem_set = 1;
    }

    int nb = (NN + 1023) / 1024;

    // CSR + normalization build
    cudaMemsetAsync(p_degi, 0, NN * sizeof(int));
    k_count<<<(EE + 255) / 256, 256>>>(ei);
    k_scan1<<<nb, 1024>>>();
    k_scan2<<<1, 64>>>(nb);
    k_scan3<<<nb, 1024>>>();
    k_fill<<<(EE + 255) / 256, 256>>>(ei);

    int gemm_blocks = (NN + 127) / 128;
    int agg_blocks  = (NN * 32 + 255) / 256;

    k_gemm2<<<gemm_blocks, 256, SM_TOTAL_BYTES>>>(x, c1w, p_z, NN);
    k_agg<<<agg_blocks, 256>>>(p_z, c1b, p_h, 1);
    k_gemm2<<<gemm_blocks, 256, SM_TOTAL_BYTES>>>(p_h, c2w, p_z, NN);
    k_agg<<<agg_blocks, 256>>>(p_z, c2b, p_h, 1);
    k_gemm2<<<gemm_blocks, 256, SM_TOTAL_BYTES>>>(p_h, c3w, p_z, NN);
    k_agg<<<agg_blocks, 256>>>(p_z, c3b, p_h, 0);

    k_pool<<<GG, 128>>>(p_h, batch, dout);

    k_fc<<<32, 256>>>(p_f,  f1w, f1b, p_t1, 128,  1024, 1);
    k_fc<<<16, 256>>>(p_t1, f2w, f2b, p_t2, 1024, 512,  1);
    k_fc<<<8,  256>>>(p_t2, f3w, f3b, p_t3, 512,  256,  1);
    k_fc<<<4,  256>>>(p_t3, f4w, f4b, p_t4, 256,  128,  1);
    k_fc<<<1,  256>>>(p_t4, f5w, f5b, dout + GG * HD, 128, 10, 0);
}

// round 5
// speedup vs baseline: 1.0649x; 1.0649x over previous
#include <cuda_runtime.h>
#include <math.h>
#include <stdint.h>

#define NN 50000
#define EE 800000
#define HD 128
#define GG 64

// ---------------- scratch (device globals: allocation-free) ----------------
__device__ float g_z[NN * HD];        // GEMM output (UNscaled xW)
__device__ float g_h[NN * HD];
__device__ float g_dinv[NN];
__device__ int   g_degi[NN];
__device__ int   g_rowptr[NN + 1];
__device__ int   g_cursor[NN];
__device__ int   g_col[EE];
__device__ int   g_bsum[64];
__device__ float g_f[GG * HD];
__device__ float g_t1[GG * 1024];
__device__ float g_t2[GG * 512];
__device__ float g_t3[GG * 256];
__device__ float g_t4[GG * HD];

// ---------------- CSR build ----------------
__global__ void k_count(const int* __restrict__ ei) {
    int e = blockIdx.x * blockDim.x + threadIdx.x;
    if (e < EE) atomicAdd(&g_degi[ei[EE + e]], 1);
}
__global__ void k_scan1() {
    __shared__ int s[1024];
    int t = threadIdx.x;
    int i = blockIdx.x * 1024 + t;
    int v = (i < NN) ? g_degi[i] : 0;
    s[t] = v;
    __syncthreads();
    for (int off = 1; off < 1024; off <<= 1) {
        int x = (t >= off) ? s[t - off] : 0;
        __syncthreads();
        s[t] += x;
        __syncthreads();
    }
    if (i < NN) g_rowptr[i] = s[t] - v;
    if (t == 1023) g_bsum[blockIdx.x] = s[1023];
}
// merged scan2+scan3: each block computes its own offset from g_bsum
__global__ void k_scan3(int nb) {
    __shared__ int sb[64];
    __shared__ int off_s;
    int t = threadIdx.x;
    if (t < nb) sb[t] = g_bsum[t];
    __syncthreads();
    if (t == 0) {
        int s = 0;
        for (int i = 0; i < blockIdx.x; i++) s += sb[i];
        off_s = s;
    }
    __syncthreads();
    int i = blockIdx.x * 1024 + t;
    if (i < NN) {
        int rp = g_rowptr[i] + off_s;
        g_rowptr[i] = rp;
        g_cursor[i] = rp;
        g_dinv[i]   = rsqrtf((float)(g_degi[i] + 1));
    }
    if (i == 0) g_rowptr[NN] = EE;
}
__global__ void k_fill(const int* __restrict__ ei) {
    int e = blockIdx.x * blockDim.x + threadIdx.x;
    if (e < EE) {
        int src = ei[e];
        int dst = ei[EE + e];
        int p = atomicAdd(&g_cursor[dst], 1);
        g_col[p] = src;
    }
}

// ---------------- SGEMM: C = A @ W (no scaling) -----------------------------
// M x 128 @ 128 x 128.  BM=64 BN=128 BK=16 TM=8 TN=4, 256 threads. (round-1)
__global__ __launch_bounds__(256) void k_gemm(const float* __restrict__ A,
                                              const float* __restrict__ B,
                                              float* __restrict__ C,
                                              int M) {
    __shared__ float  As[16][65];
    __shared__ float4 Bs[16][32];
    int tid  = threadIdx.x;
    int base = blockIdx.x * 64;
    int tm = tid >> 5;
    int tn = tid & 31;
    float acc[8][4];
#pragma unroll
    for (int i = 0; i < 8; i++)
#pragma unroll
        for (int j = 0; j < 4; j++) acc[i][j] = 0.f;

    int arow  = tid >> 2;
    int acol4 = (tid & 3) * 4;
    int brow  = tid >> 5;
    int bcol  = tid & 31;

    for (int k0 = 0; k0 < 128; k0 += 16) {
        float4 av;
        int gr = base + arow;
        if (gr < M) av = *(const float4*)(A + (size_t)gr * 128 + k0 + acol4);
        else        av = make_float4(0.f, 0.f, 0.f, 0.f);
        As[acol4 + 0][arow] = av.x;
        As[acol4 + 1][arow] = av.y;
        As[acol4 + 2][arow] = av.z;
        As[acol4 + 3][arow] = av.w;
        Bs[brow][bcol]     = *(const float4*)(B + (k0 + brow) * 128 + bcol * 4);
        Bs[brow + 8][bcol] = *(const float4*)(B + (k0 + brow + 8) * 128 + bcol * 4);
        __syncthreads();
#pragma unroll
        for (int kk = 0; kk < 16; kk++) {
            float4 b4 = Bs[kk][tn];
#pragma unroll
            for (int i = 0; i < 8; i++) {
                float a = As[kk][tm * 8 + i];
                acc[i][0] = fmaf(a, b4.x, acc[i][0]);
                acc[i][1] = fmaf(a, b4.y, acc[i][1]);
                acc[i][2] = fmaf(a, b4.z, acc[i][2]);
                acc[i][3] = fmaf(a, b4.w, acc[i][3]);
            }
        }
        __syncthreads();
    }
#pragma unroll
    for (int i = 0; i < 8; i++) {
        int r = base + tm * 8 + i;
        if (r < M) {
            float4 o = make_float4(acc[i][0], acc[i][1], acc[i][2], acc[i][3]);
            *(float4*)(C + (size_t)r * 128 + tn * 4) = o;
        }
    }
}

// ---------------- aggregation: one warp per node ----------------
// out[v] = dinv[v] * ( dinv[v]*z[v] + sum_u dinv[u]*z[u] ) + bias
__global__ __launch_bounds__(256) void k_agg(const float* __restrict__ z,
                                             const float* __restrict__ bias,
                                             float* __restrict__ out,
                                             int relu) {
    int wid  = (blockIdx.x * blockDim.x + threadIdx.x) >> 5;
    int lane = threadIdx.x & 31;
    if (wid >= NN) return;
    const float4* z4 = (const float4*)z;
    float dv = g_dinv[wid];
    float4 zs = z4[(size_t)wid * 32 + lane];
    float4 acc;
    acc.x = zs.x * dv; acc.y = zs.y * dv; acc.z = zs.z * dv; acc.w = zs.w * dv;
    int beg = g_rowptr[wid];
    int end = g_rowptr[wid + 1];
    int j = beg;
    for (; j + 3 < end; j += 4) {
        int u0 = g_col[j], u1 = g_col[j + 1], u2 = g_col[j + 2], u3 = g_col[j + 3];
        float d0 = g_dinv[u0], d1 = g_dinv[u1], d2 = g_dinv[u2], d3 = g_dinv[u3];
        float4 a = z4[(size_t)u0 * 32 + lane];
        float4 b = z4[(size_t)u1 * 32 + lane];
        float4 c = z4[(size_t)u2 * 32 + lane];
        float4 d = z4[(size_t)u3 * 32 + lane];
        acc.x = fmaf(d0, a.x, acc.x); acc.y = fmaf(d0, a.y, acc.y);
        acc.z = fmaf(d0, a.z, acc.z); acc.w = fmaf(d0, a.w, acc.w);
        acc.x = fmaf(d1, b.x, acc.x); acc.y = fmaf(d1, b.y, acc.y);
        acc.z = fmaf(d1, b.z, acc.z); acc.w = fmaf(d1, b.w, acc.w);
        acc.x = fmaf(d2, c.x, acc.x); acc.y = fmaf(d2, c.y, acc.y);
        acc.z = fmaf(d2, c.z, acc.z); acc.w = fmaf(d2, c.w, acc.w);
        acc.x = fmaf(d3, d.x, acc.x); acc.y = fmaf(d3, d.y, acc.y);
        acc.z = fmaf(d3, d.z, acc.z); acc.w = fmaf(d3, d.w, acc.w);
    }
    for (; j < end; j++) {
        int u = g_col[j];
        float du = g_dinv[u];
        float4 a = z4[(size_t)u * 32 + lane];
        acc.x = fmaf(du, a.x, acc.x); acc.y = fmaf(du, a.y, acc.y);
        acc.z = fmaf(du, a.z, acc.z); acc.w = fmaf(du, a.w, acc.w);
    }
    float4 bb = ((const float4*)bias)[lane];
    float4 r;
    r.x = fmaf(acc.x, dv, bb.x);
    r.y = fmaf(acc.y, dv, bb.y);
    r.z = fmaf(acc.z, dv, bb.z);
    r.w = fmaf(acc.w, dv, bb.w);
    if (relu) {
        r.x = fmaxf(r.x, 0.f); r.y = fmaxf(r.y, 0.f);
        r.z = fmaxf(r.z, 0.f); r.w = fmaxf(r.w, 0.f);
    }
    ((float4*)out)[(size_t)wid * 32 + lane] = r;
}

// ---------------- mean pool per graph ----------------
__global__ __launch_bounds__(128) void k_pool(const float* __restrict__ h,
                                              const int* __restrict__ batch,
                                              float* __restrict__ dout) {
    int g = blockIdx.x;
    int c = threadIdx.x;
    int lo = 0, hi = NN;
    while (lo < hi) { int m = (lo + hi) >> 1; if (batch[m] < g) lo = m + 1; else hi = m; }
    int start = lo;
    lo = 0; hi = NN;
    while (lo < hi) { int m = (lo + hi) >> 1; if (batch[m] < g + 1) lo = m + 1; else hi = m; }
    int end = lo;
    float s = 0.f;
    for (int v = start; v < end; v++) s += h[(size_t)v * 128 + c];
    float cnt = (float)(end - start);
    float val = s / fmaxf(cnt, 1.0f);
    g_f[g * 128 + c] = val;
    dout[g * 128 + c] = val;
}

// ---------------- MLP layer: 64 graphs x 32-col slice per block ------------
__global__ __launch_bounds__(256) void k_fc(const float* __restrict__ in,
                                            const float* __restrict__ W,
                                            const float* __restrict__ b,
                                            float* __restrict__ out,
                                            int K, int C, int relu) {
    __shared__ float s_in[64 * 64];
    int tx = threadIdx.x & 31;
    int ty = threadIdx.x >> 5;
    int c  = blockIdx.x * 32 + tx;
    int ce = (c < C) ? c : (C - 1);
    float acc[8];
    #pragma unroll
    for (int j = 0; j < 8; j++) acc[j] = 0.f;
    for (int k0 = 0; k0 < K; k0 += 64) {
        #pragma unroll
        for (int i = 0; i < 16; i++) {
            int idx = i * 256 + threadIdx.x;
            int g = idx >> 6, k = idx & 63;
            s_in[idx] = in[(size_t)g * K + k0 + k];
        }
        __syncthreads();
        #pragma unroll 4
        for (int k = 0; k < 64; k++) {
            float w = W[(size_t)(k0 + k) * C + ce];
            #pragma unroll
            for (int j = 0; j < 8; j++)
                acc[j] = fmaf(s_in[(ty * 8 + j) * 64 + k], w, acc[j]);
        }
        __syncthreads();
    }
    if (c < C) {
        float bias = b[c];
        #pragma unroll
        for (int j = 0; j < 8; j++) {
            float v = acc[j] + bias;
            if (relu) v = fmaxf(v, 0.f);
            out[(size_t)(ty * 8 + j) * C + c] = v;
        }
    }
}

extern "C" void kernel_launch(void* const* d_in, const int* in_sizes, int n_in,
                              void* d_out, int out_size) {
    const float* x     = (const float*)d_in[0];
    const int*   ei    = (const int*)d_in[1];
    const int*   batch = (const int*)d_in[2];
    const float* c1w = (const float*)d_in[3];
    const float* c1b = (const float*)d_in[4];
    const float* c2w = (const float*)d_in[5];
    const float* c2b = (const float*)d_in[6];
    const float* c3w = (const float*)d_in[7];
    const float* c3b = (const float*)d_in[8];
    const float* f1w = (const float*)d_in[9];
    const float* f1b = (const float*)d_in[10];
    const float* f2w = (const float*)d_in[11];
    const float* f2b = (const float*)d_in[12];
    const float* f3w = (const float*)d_in[13];
    const float* f3b = (const float*)d_in[14];
    const float* f4w = (const float*)d_in[15];
    const float* f4b = (const float*)d_in[16];
    const float* f5w = (const float*)d_in[17];
    const float* f5b = (const float*)d_in[18];
    float* dout = (float*)d_out;

    float *p_z, *p_h, *p_f, *p_t1, *p_t2, *p_t3, *p_t4;
    int* p_degi;
    cudaGetSymbolAddress((void**)&p_z,  g_z);
    cudaGetSymbolAddress((void**)&p_h,  g_h);
    cudaGetSymbolAddress((void**)&p_f,  g_f);
    cudaGetSymbolAddress((void**)&p_t1, g_t1);
    cudaGetSymbolAddress((void**)&p_t2, g_t2);
    cudaGetSymbolAddress((void**)&p_t3, g_t3);
    cudaGetSymbolAddress((void**)&p_t4, g_t4);
    cudaGetSymbolAddress((void**)&p_degi, g_degi);

    static cudaStream_t s2 = 0;
    static cudaEvent_t evA = 0, evB = 0;
    if (!s2) {
        cudaStreamCreateWithFlags(&s2, cudaStreamNonBlocking);
        cudaEventCreateWithFlags(&evA, cudaEventDisableTiming);
        cudaEventCreateWithFlags(&evB, cudaEventDisableTiming);
    }

    int nb = (NN + 1023) / 1024;
    int gemm_blocks = (NN + 63) / 64;
    int agg_blocks  = (NN * 32 + 255) / 256;

    // fork: CSR build on s2, conv1 GEMM on main stream (independent)
    cudaEventRecord(evA, 0);
    cudaStreamWaitEvent(s2, evA, 0);
    cudaMemsetAsync(p_degi, 0, NN * sizeof(int), s2);
    k_count<<<(EE + 255) / 256, 256, 0, s2>>>(ei);
    k_scan1<<<nb, 1024, 0, s2>>>();
    k_scan3<<<nb, 1024, 0, s2>>>(nb);
    k_fill<<<(EE + 255) / 256, 256, 0, s2>>>(ei);
    cudaEventRecord(evB, s2);

    k_gemm<<<gemm_blocks, 256>>>(x, c1w, p_z, NN);   // main stream, overlaps CSR

    cudaStreamWaitEvent(0, evB, 0);                  // join before agg1

    k_agg<<<agg_blocks, 256>>>(p_z, c1b, p_h, 1);
    k_gemm<<<gemm_blocks, 256>>>(p_h, c2w, p_z, NN);
    k_agg<<<agg_blocks, 256>>>(p_z, c2b, p_h, 1);
    k_gemm<<<gemm_blocks, 256>>>(p_h, c3w, p_z, NN);
    k_agg<<<agg_blocks, 256>>>(p_z, c3b, p_h, 0);

    k_pool<<<GG, 128>>>(p_h, batch, dout);

    k_fc<<<32, 256>>>(p_f,  f1w, f1b, p_t1, 128,  1024, 1);
    k_fc<<<16, 256>>>(p_t1, f2w, f2b, p_t2, 1024, 512,  1);
    k_fc<<<8,  256>>>(p_t2, f3w, f3b, p_t3, 512,  256,  1);
    k_fc<<<4,  256>>>(p_t3, f4w, f4b, p_t4, 256,  128,  1);
    k_fc<<<1,  256>>>(p_t4, f5w, f5b, dout + GG * HD, 128, 10, 0);
}

// round 6
// speedup vs baseline: 1.8788x; 1.7643x over previous
#include <cuda_runtime.h>
#include <math.h>
#include <stdint.h>

#define NN 50000
#define EE 800000
#define HD 128
#define GG 64

// ---------------- scratch (device globals: allocation-free) ----------------
__device__ float g_z[NN * HD];        // GEMM output (dinv-scaled)
__device__ float g_h[NN * HD];
__device__ float g_dinv[NN];
__device__ int   g_degi[NN];
__device__ int   g_rowptr[NN + 1];
__device__ int   g_cursor[NN];
__device__ int   g_col[EE];
__device__ int   g_bsum[64];
__device__ float g_f[GG * HD];
__device__ float g_t1[GG * 1024];
__device__ float g_t2[GG * 512];
__device__ float g_t3[GG * 256];
__device__ float g_t4[GG * HD];

// ---------------- CSR build ----------------
__global__ void k_count(const int* __restrict__ ei) {
    int e = blockIdx.x * blockDim.x + threadIdx.x;
    if (e < EE) atomicAdd(&g_degi[ei[EE + e]], 1);
}
__global__ void k_scan1() {
    __shared__ int s[1024];
    int t = threadIdx.x;
    int i = blockIdx.x * 1024 + t;
    int v = (i < NN) ? g_degi[i] : 0;
    s[t] = v;
    __syncthreads();
    for (int off = 1; off < 1024; off <<= 1) {
        int x = (t >= off) ? s[t - off] : 0;
        __syncthreads();
        s[t] += x;
        __syncthreads();
    }
    if (i < NN) g_rowptr[i] = s[t] - v;
    if (t == 1023) g_bsum[blockIdx.x] = s[1023];
}
// merged scan2+scan3: each block computes its own offset from g_bsum
__global__ void k_scan3(int nb) {
    __shared__ int sb[64];
    __shared__ int off_s;
    int t = threadIdx.x;
    if (t < nb) sb[t] = g_bsum[t];
    __syncthreads();
    if (t == 0) {
        int s = 0;
        for (int i = 0; i < blockIdx.x; i++) s += sb[i];
        off_s = s;
    }
    __syncthreads();
    int i = blockIdx.x * 1024 + t;
    if (i < NN) {
        int rp = g_rowptr[i] + off_s;
        g_rowptr[i] = rp;
        g_cursor[i] = rp;
        g_dinv[i]   = rsqrtf((float)(g_degi[i] + 1));
    }
    if (i == 0) g_rowptr[NN] = EE;
}
__global__ void k_fill(const int* __restrict__ ei) {
    int e = blockIdx.x * blockDim.x + threadIdx.x;
    if (e < EE) {
        int src = ei[e];
        int dst = ei[EE + e];
        int p = atomicAdd(&g_cursor[dst], 1);
        g_col[p] = src;
    }
}

// ---------------- SGEMM: C[v][c] = dinv[v] * sum_k A[v][k]*B[k][c] ----------
// M x 128 @ 128 x 128.  BM=64 BN=128 BK=16, 128 threads, TM=8 TN=8.
__global__ __launch_bounds__(128) void k_gemm(const float* __restrict__ A,
                                              const float* __restrict__ B,
                                              float* __restrict__ C,
                                              int M) {
    __shared__ float  As[16][65];     // [k][row]
    __shared__ float4 Bs[16][32];     // [k][col4]
    int tid  = threadIdx.x;
    int base = blockIdx.x * 64;
    int tx = tid & 15;                // col group: cols tx*8 .. tx*8+7
    int ty = tid >> 4;                // row group: rows ty*8 .. ty*8+7
    float acc[8][8];
#pragma unroll
    for (int i = 0; i < 8; i++)
#pragma unroll
        for (int j = 0; j < 8; j++) acc[i][j] = 0.f;

    for (int k0 = 0; k0 < 128; k0 += 16) {
        // stage A: 64 rows x 16 k = 256 float4, 2 per thread, transpose to As[k][row]
#pragma unroll
        for (int i = 0; i < 2; i++) {
            int idx = i * 128 + tid;          // 0..255
            int row = idx >> 2;               // 0..63
            int k4  = (idx & 3) * 4;          // 0,4,8,12
            float4 av;
            int gr = base + row;
            if (gr < M) av = *(const float4*)(A + (size_t)gr * 128 + k0 + k4);
            else        av = make_float4(0.f, 0.f, 0.f, 0.f);
            As[k4 + 0][row] = av.x;
            As[k4 + 1][row] = av.y;
            As[k4 + 2][row] = av.z;
            As[k4 + 3][row] = av.w;
        }
        // stage B: 16 k x 128 col = 512 float4, 4 per thread
#pragma unroll
        for (int i = 0; i < 4; i++) {
            int idx = i * 128 + tid;          // 0..511
            int k  = idx >> 5;                // 0..15
            int c  = idx & 31;                // 0..31 (float4 index)
            Bs[k][c] = *(const float4*)(B + (size_t)(k0 + k) * 128 + c * 4);
        }
        __syncthreads();

#pragma unroll
        for (int kk = 0; kk < 16; kk++) {
            float ar[8];
#pragma unroll
            for (int i = 0; i < 8; i++) ar[i] = As[kk][ty * 8 + i];
            float4 b0 = Bs[kk][tx * 2];
            float4 b1 = Bs[kk][tx * 2 + 1];
#pragma unroll
            for (int i = 0; i < 8; i++) {
                float a = ar[i];
                acc[i][0] = fmaf(a, b0.x, acc[i][0]);
                acc[i][1] = fmaf(a, b0.y, acc[i][1]);
                acc[i][2] = fmaf(a, b0.z, acc[i][2]);
                acc[i][3] = fmaf(a, b0.w, acc[i][3]);
                acc[i][4] = fmaf(a, b1.x, acc[i][4]);
                acc[i][5] = fmaf(a, b1.y, acc[i][5]);
                acc[i][6] = fmaf(a, b1.z, acc[i][6]);
                acc[i][7] = fmaf(a, b1.w, acc[i][7]);
            }
        }
        __syncthreads();
    }

    // epilogue: scale by dinv[row], two float4 stores per row
#pragma unroll
    for (int i = 0; i < 8; i++) {
        int r = base + ty * 8 + i;
        if (r < M) {
            float dv = g_dinv[r];
            float4 o0 = make_float4(acc[i][0] * dv, acc[i][1] * dv,
                                    acc[i][2] * dv, acc[i][3] * dv);
            float4 o1 = make_float4(acc[i][4] * dv, acc[i][5] * dv,
                                    acc[i][6] * dv, acc[i][7] * dv);
            *(float4*)(C + (size_t)r * 128 + tx * 8)     = o0;
            *(float4*)(C + (size_t)r * 128 + tx * 8 + 4) = o1;
        }
    }
}

// ---------------- aggregation: one warp per node (round-1 exact) -----------
// out[v] = dinv[v] * (z[v] + sum_{u in in(v)} z[u]) + bias ; optional relu
__global__ __launch_bounds__(256) void k_agg(const float* __restrict__ z,
                                             const float* __restrict__ bias,
                                             float* __restrict__ out,
                                             int relu) {
    int wid  = (blockIdx.x * blockDim.x + threadIdx.x) >> 5;
    int lane = threadIdx.x & 31;
    if (wid >= NN) return;
    const float4* z4 = (const float4*)z;
    float4 acc = z4[(size_t)wid * 32 + lane];   // self loop
    int beg = g_rowptr[wid];
    int end = g_rowptr[wid + 1];
    int j = beg;
    for (; j + 3 < end; j += 4) {
        int u0 = g_col[j], u1 = g_col[j + 1], u2 = g_col[j + 2], u3 = g_col[j + 3];
        float4 a = z4[(size_t)u0 * 32 + lane];
        float4 b = z4[(size_t)u1 * 32 + lane];
        float4 c = z4[(size_t)u2 * 32 + lane];
        float4 d = z4[(size_t)u3 * 32 + lane];
        acc.x += (a.x + b.x) + (c.x + d.x);
        acc.y += (a.y + b.y) + (c.y + d.y);
        acc.z += (a.z + b.z) + (c.z + d.z);
        acc.w += (a.w + b.w) + (c.w + d.w);
    }
    for (; j < end; j++) {
        float4 a = z4[(size_t)g_col[j] * 32 + lane];
        acc.x += a.x; acc.y += a.y; acc.z += a.z; acc.w += a.w;
    }
    float dv = g_dinv[wid];
    float4 bb = ((const float4*)bias)[lane];
    float4 r;
    r.x = fmaf(acc.x, dv, bb.x);
    r.y = fmaf(acc.y, dv, bb.y);
    r.z = fmaf(acc.z, dv, bb.z);
    r.w = fmaf(acc.w, dv, bb.w);
    if (relu) {
        r.x = fmaxf(r.x, 0.f); r.y = fmaxf(r.y, 0.f);
        r.z = fmaxf(r.z, 0.f); r.w = fmaxf(r.w, 0.f);
    }
    ((float4*)out)[(size_t)wid * 32 + lane] = r;
}

// ---------------- mean pool per graph (round-1 exact) ----------------------
__global__ __launch_bounds__(128) void k_pool(const float* __restrict__ h,
                                              const int* __restrict__ batch,
                                              float* __restrict__ dout) {
    int g = blockIdx.x;
    int c = threadIdx.x;
    int lo = 0, hi = NN;
    while (lo < hi) { int m = (lo + hi) >> 1; if (batch[m] < g) lo = m + 1; else hi = m; }
    int start = lo;
    lo = 0; hi = NN;
    while (lo < hi) { int m = (lo + hi) >> 1; if (batch[m] < g + 1) lo = m + 1; else hi = m; }
    int end = lo;
    float s = 0.f;
    for (int v = start; v < end; v++) s += h[(size_t)v * 128 + c];
    float cnt = (float)(end - start);
    float val = s / fmaxf(cnt, 1.0f);
    g_f[g * 128 + c] = val;
    dout[g * 128 + c] = val;
}

// ---------------- MLP layer (round-1 exact: one graph x 256 cols / block) --
__global__ __launch_bounds__(256) void k_fc(const float* __restrict__ in,
                                            const float* __restrict__ W,
                                            const float* __restrict__ b,
                                            float* __restrict__ out,
                                            int K, int C, int relu) {
    __shared__ float s_in[1024];
    int g = blockIdx.x;
    for (int k = threadIdx.x; k < K; k += blockDim.x) s_in[k] = in[g * K + k];
    __syncthreads();
    int c = blockIdx.y * blockDim.x + threadIdx.x;
    if (c < C) {
        float acc = b[c];
        for (int k = 0; k < K; k++) acc = fmaf(s_in[k], W[(size_t)k * C + c], acc);
        if (relu) acc = fmaxf(acc, 0.f);
        out[g * C + c] = acc;
    }
}

extern "C" void kernel_launch(void* const* d_in, const int* in_sizes, int n_in,
                              void* d_out, int out_size) {
    const float* x     = (const float*)d_in[0];
    const int*   ei    = (const int*)d_in[1];
    const int*   batch = (const int*)d_in[2];
    const float* c1w = (const float*)d_in[3];
    const float* c1b = (const float*)d_in[4];
    const float* c2w = (const float*)d_in[5];
    const float* c2b = (const float*)d_in[6];
    const float* c3w = (const float*)d_in[7];
    const float* c3b = (const float*)d_in[8];
    const float* f1w = (const float*)d_in[9];
    const float* f1b = (const float*)d_in[10];
    const float* f2w = (const float*)d_in[11];
    const float* f2b = (const float*)d_in[12];
    const float* f3w = (const float*)d_in[13];
    const float* f3b = (const float*)d_in[14];
    const float* f4w = (const float*)d_in[15];
    const float* f4b = (const float*)d_in[16];
    const float* f5w = (const float*)d_in[17];
    const float* f5b = (const float*)d_in[18];
    float* dout = (float*)d_out;

    float *p_z, *p_h, *p_f, *p_t1, *p_t2, *p_t3, *p_t4;
    int* p_degi;
    cudaGetSymbolAddress((void**)&p_z,  g_z);
    cudaGetSymbolAddress((void**)&p_h,  g_h);
    cudaGetSymbolAddress((void**)&p_f,  g_f);
    cudaGetSymbolAddress((void**)&p_t1, g_t1);
    cudaGetSymbolAddress((void**)&p_t2, g_t2);
    cudaGetSymbolAddress((void**)&p_t3, g_t3);
    cudaGetSymbolAddress((void**)&p_t4, g_t4);
    cudaGetSymbolAddress((void**)&p_degi, g_degi);

    int nb = (NN + 1023) / 1024;

    // CSR + normalization build (single stream)
    cudaMemsetAsync(p_degi, 0, NN * sizeof(int));
    k_count<<<(EE + 255) / 256, 256>>>(ei);
    k_scan1<<<nb, 1024>>>();
    k_scan3<<<nb, 1024>>>(nb);
    k_fill<<<(EE + 255) / 256, 256>>>(ei);

    int gemm_blocks = (NN + 63) / 64;
    int agg_blocks  = (NN * 32 + 255) / 256;

    // conv1
    k_gemm<<<gemm_blocks, 128>>>(x, c1w, p_z, NN);
    k_agg<<<agg_blocks, 256>>>(p_z, c1b, p_h, 1);
    // conv2
    k_gemm<<<gemm_blocks, 128>>>(p_h, c2w, p_z, NN);
    k_agg<<<agg_blocks, 256>>>(p_z, c2b, p_h, 1);
    // conv3 (no relu)
    k_gemm<<<gemm_blocks, 128>>>(p_h, c3w, p_z, NN);
    k_agg<<<agg_blocks, 256>>>(p_z, c3b, p_h, 0);

    // mean pool -> f (first part of output)
    k_pool<<<GG, 128>>>(p_h, batch, dout);

    // MLP head (round-1 per-graph tiling)
    k_fc<<<dim3(GG, (1024 + 255) / 256), 256>>>(p_f,  f1w, f1b, p_t1, 128,  1024, 1);
    k_fc<<<dim3(GG, (512  + 255) / 256), 256>>>(p_t1, f2w, f2b, p_t2, 1024, 512,  1);
    k_fc<<<dim3(GG, (256  + 255) / 256), 256>>>(p_t2, f3w, f3b, p_t3, 512,  256,  1);
    k_fc<<<dim3(GG, (128  + 255) / 256), 256>>>(p_t3, f4w, f4b, p_t4, 256,  128,  1);
    k_fc<<<dim3(GG, 1), 256>>>(p_t4, f5w, f5b, dout + GG * HD, 128, 10, 0);
}

// round 7
// speedup vs baseline: 2.0189x; 1.0745x over previous
#include <cuda_runtime.h>
#include <math.h>
#include <stdint.h>

#define NN 50000
#define EE 800000
#define HD 128
#define GG 64

// ---------------- scratch (device globals: allocation-free) ----------------
__device__ float g_z[NN * HD];        // GEMM output (dinv-scaled)
__device__ float g_h[NN * HD];
__device__ float g_dinv[NN];
__device__ int   g_degi[NN];
__device__ int   g_rowptr[NN + 1];
__device__ int   g_cursor[NN];
__device__ int   g_col[EE];
__device__ int   g_bsum[64];
__device__ float g_f[GG * HD];
__device__ float g_t1[GG * 1024];
__device__ float g_t2[GG * 512];
__device__ float g_t3[GG * 256];
__device__ float g_t4[GG * HD];

// ---------------- CSR build ----------------
__global__ void k_count(const int* __restrict__ ei) {
    int e = blockIdx.x * blockDim.x + threadIdx.x;
    if (e < EE) atomicAdd(&g_degi[ei[EE + e]], 1);
}
__global__ void k_scan1() {
    __shared__ int s[1024];
    int t = threadIdx.x;
    int i = blockIdx.x * 1024 + t;
    int v = (i < NN) ? g_degi[i] : 0;
    s[t] = v;
    __syncthreads();
    for (int off = 1; off < 1024; off <<= 1) {
        int x = (t >= off) ? s[t - off] : 0;
        __syncthreads();
        s[t] += x;
        __syncthreads();
    }
    if (i < NN) g_rowptr[i] = s[t] - v;
    if (t == 1023) g_bsum[blockIdx.x] = s[1023];
}
// merged scan2+scan3
__global__ void k_scan3(int nb) {
    __shared__ int sb[64];
    __shared__ int off_s;
    int t = threadIdx.x;
    if (t < nb) sb[t] = g_bsum[t];
    __syncthreads();
    if (t == 0) {
        int s = 0;
        for (int i = 0; i < blockIdx.x; i++) s += sb[i];
        off_s = s;
    }
    __syncthreads();
    int i = blockIdx.x * 1024 + t;
    if (i < NN) {
        int rp = g_rowptr[i] + off_s;
        g_rowptr[i] = rp;
        g_cursor[i] = rp;
        g_dinv[i]   = rsqrtf((float)(g_degi[i] + 1));
    }
    if (i == 0) g_rowptr[NN] = EE;
}
__global__ void k_fill(const int* __restrict__ ei) {
    int e = blockIdx.x * blockDim.x + threadIdx.x;
    if (e < EE) {
        int src = ei[e];
        int dst = ei[EE + e];
        int p = atomicAdd(&g_cursor[dst], 1);
        g_col[p] = src;
    }
}

// ---------------- SGEMM (round-1 exact shape): C = dinv[r]*(A@W) -----------
// BM=64 BN=128 BK=16 TM=8 TN=4, 256 threads.
// NOTE: conv1's GEMM runs concurrently with the CSR chain; it must not read
// g_dinv (computed by scan3). Scaling moved to a flag: scale==0 -> raw store
// is NOT needed because scaling by dinv commutes; instead we keep dinv in
// epilogue but gemm1 is ordered AFTER scan3 via the event when scale==1.
__global__ __launch_bounds__(256) void k_gemm(const float* __restrict__ A,
                                              const float* __restrict__ B,
                                              float* __restrict__ C,
                                              int M) {
    __shared__ float  As[16][65];
    __shared__ float4 Bs[16][32];
    int tid  = threadIdx.x;
    int base = blockIdx.x * 64;
    int tm = tid >> 5;
    int tn = tid & 31;
    float acc[8][4];
#pragma unroll
    for (int i = 0; i < 8; i++)
#pragma unroll
        for (int j = 0; j < 4; j++) acc[i][j] = 0.f;

    int arow  = tid >> 2;
    int acol4 = (tid & 3) * 4;
    int brow  = tid >> 5;
    int bcol  = tid & 31;

    for (int k0 = 0; k0 < 128; k0 += 16) {
        float4 av;
        int gr = base + arow;
        if (gr < M) av = *(const float4*)(A + (size_t)gr * 128 + k0 + acol4);
        else        av = make_float4(0.f, 0.f, 0.f, 0.f);
        As[acol4 + 0][arow] = av.x;
        As[acol4 + 1][arow] = av.y;
        As[acol4 + 2][arow] = av.z;
        As[acol4 + 3][arow] = av.w;
        Bs[brow][bcol]     = *(const float4*)(B + (k0 + brow) * 128 + bcol * 4);
        Bs[brow + 8][bcol] = *(const float4*)(B + (k0 + brow + 8) * 128 + bcol * 4);
        __syncthreads();
#pragma unroll
        for (int kk = 0; kk < 16; kk++) {
            float4 b4 = Bs[kk][tn];
#pragma unroll
            for (int i = 0; i < 8; i++) {
                float a = As[kk][tm * 8 + i];
                acc[i][0] = fmaf(a, b4.x, acc[i][0]);
                acc[i][1] = fmaf(a, b4.y, acc[i][1]);
                acc[i][2] = fmaf(a, b4.z, acc[i][2]);
                acc[i][3] = fmaf(a, b4.w, acc[i][3]);
            }
        }
        __syncthreads();
    }
#pragma unroll
    for (int i = 0; i < 8; i++) {
        int r = base + tm * 8 + i;
        if (r < M) {
            float dv = g_dinv[r];
            float4 o;
            o.x = acc[i][0] * dv;
            o.y = acc[i][1] * dv;
            o.z = acc[i][2] * dv;
            o.w = acc[i][3] * dv;
            *(float4*)(C + (size_t)r * 128 + tn * 4) = o;
        }
    }
}

// gemm1 variant: NO dinv read (safe to overlap with CSR build); stores raw xW
__global__ __launch_bounds__(256) void k_gemm_raw(const float* __restrict__ A,
                                                  const float* __restrict__ B,
                                                  float* __restrict__ C,
                                                  int M) {
    __shared__ float  As[16][65];
    __shared__ float4 Bs[16][32];
    int tid  = threadIdx.x;
    int base = blockIdx.x * 64;
    int tm = tid >> 5;
    int tn = tid & 31;
    float acc[8][4];
#pragma unroll
    for (int i = 0; i < 8; i++)
#pragma unroll
        for (int j = 0; j < 4; j++) acc[i][j] = 0.f;

    int arow  = tid >> 2;
    int acol4 = (tid & 3) * 4;
    int brow  = tid >> 5;
    int bcol  = tid & 31;

    for (int k0 = 0; k0 < 128; k0 += 16) {
        float4 av;
        int gr = base + arow;
        if (gr < M) av = *(const float4*)(A + (size_t)gr * 128 + k0 + acol4);
        else        av = make_float4(0.f, 0.f, 0.f, 0.f);
        As[acol4 + 0][arow] = av.x;
        As[acol4 + 1][arow] = av.y;
        As[acol4 + 2][arow] = av.z;
        As[acol4 + 3][arow] = av.w;
        Bs[brow][bcol]     = *(const float4*)(B + (k0 + brow) * 128 + bcol * 4);
        Bs[brow + 8][bcol] = *(const float4*)(B + (k0 + brow + 8) * 128 + bcol * 4);
        __syncthreads();
#pragma unroll
        for (int kk = 0; kk < 16; kk++) {
            float4 b4 = Bs[kk][tn];
#pragma unroll
            for (int i = 0; i < 8; i++) {
                float a = As[kk][tm * 8 + i];
                acc[i][0] = fmaf(a, b4.x, acc[i][0]);
                acc[i][1] = fmaf(a, b4.y, acc[i][1]);
                acc[i][2] = fmaf(a, b4.z, acc[i][2]);
                acc[i][3] = fmaf(a, b4.w, acc[i][3]);
            }
        }
        __syncthreads();
    }
#pragma unroll
    for (int i = 0; i < 8; i++) {
        int r = base + tm * 8 + i;
        if (r < M) {
            float4 o = make_float4(acc[i][0], acc[i][1], acc[i][2], acc[i][3]);
            *(float4*)(C + (size_t)r * 128 + tn * 4) = o;
        }
    }
}

// ---------------- aggregation (round-1 exact), with optional self-scale ----
// scale_self=1: z is raw xW -> out[v] = dinv[v]*(dinv[v]*z[v] + sum dinv[u]*z[u]) + b
// scale_self=0: z is already dinv-scaled -> round-1 formula
__global__ __launch_bounds__(256) void k_agg(const float* __restrict__ z,
                                             const float* __restrict__ bias,
                                             float* __restrict__ out,
                                             int relu, int scale_self) {
    int wid  = (blockIdx.x * blockDim.x + threadIdx.x) >> 5;
    int lane = threadIdx.x & 31;
    if (wid >= NN) return;
    const float4* z4 = (const float4*)z;
    float dv = g_dinv[wid];
    float4 acc = z4[(size_t)wid * 32 + lane];
    if (scale_self) { acc.x *= dv; acc.y *= dv; acc.z *= dv; acc.w *= dv; }
    int beg = g_rowptr[wid];
    int end = g_rowptr[wid + 1];
    int j = beg;
    if (scale_self) {
        for (; j + 1 < end; j += 2) {
            int u0 = g_col[j], u1 = g_col[j + 1];
            float d0 = g_dinv[u0], d1 = g_dinv[u1];
            float4 a = z4[(size_t)u0 * 32 + lane];
            float4 b = z4[(size_t)u1 * 32 + lane];
            acc.x = fmaf(d0, a.x, acc.x); acc.y = fmaf(d0, a.y, acc.y);
            acc.z = fmaf(d0, a.z, acc.z); acc.w = fmaf(d0, a.w, acc.w);
            acc.x = fmaf(d1, b.x, acc.x); acc.y = fmaf(d1, b.y, acc.y);
            acc.z = fmaf(d1, b.z, acc.z); acc.w = fmaf(d1, b.w, acc.w);
        }
        for (; j < end; j++) {
            int u = g_col[j];
            float du = g_dinv[u];
            float4 a = z4[(size_t)u * 32 + lane];
            acc.x = fmaf(du, a.x, acc.x); acc.y = fmaf(du, a.y, acc.y);
            acc.z = fmaf(du, a.z, acc.z); acc.w = fmaf(du, a.w, acc.w);
        }
    } else {
        for (; j + 3 < end; j += 4) {
            int u0 = g_col[j], u1 = g_col[j + 1], u2 = g_col[j + 2], u3 = g_col[j + 3];
            float4 a = z4[(size_t)u0 * 32 + lane];
            float4 b = z4[(size_t)u1 * 32 + lane];
            float4 c = z4[(size_t)u2 * 32 + lane];
            float4 d = z4[(size_t)u3 * 32 + lane];
            acc.x += (a.x + b.x) + (c.x + d.x);
            acc.y += (a.y + b.y) + (c.y + d.y);
            acc.z += (a.z + b.z) + (c.z + d.z);
            acc.w += (a.w + b.w) + (c.w + d.w);
        }
        for (; j < end; j++) {
            float4 a = z4[(size_t)g_col[j] * 32 + lane];
            acc.x += a.x; acc.y += a.y; acc.z += a.z; acc.w += a.w;
        }
    }
    float4 bb = ((const float4*)bias)[lane];
    float4 r;
    r.x = fmaf(acc.x, dv, bb.x);
    r.y = fmaf(acc.y, dv, bb.y);
    r.z = fmaf(acc.z, dv, bb.z);
    r.w = fmaf(acc.w, dv, bb.w);
    if (relu) {
        r.x = fmaxf(r.x, 0.f); r.y = fmaxf(r.y, 0.f);
        r.z = fmaxf(r.z, 0.f); r.w = fmaxf(r.w, 0.f);
    }
    ((float4*)out)[(size_t)wid * 32 + lane] = r;
}

// ---------------- mean pool per graph (round-1 exact) ----------------------
__global__ __launch_bounds__(128) void k_pool(const float* __restrict__ h,
                                              const int* __restrict__ batch,
                                              float* __restrict__ dout) {
    int g = blockIdx.x;
    int c = threadIdx.x;
    int lo = 0, hi = NN;
    while (lo < hi) { int m = (lo + hi) >> 1; if (batch[m] < g) lo = m + 1; else hi = m; }
    int start = lo;
    lo = 0; hi = NN;
    while (lo < hi) { int m = (lo + hi) >> 1; if (batch[m] < g + 1) lo = m + 1; else hi = m; }
    int end = lo;
    float s = 0.f;
    for (int v = start; v < end; v++) s += h[(size_t)v * 128 + c];
    float cnt = (float)(end - start);
    float val = s / fmaxf(cnt, 1.0f);
    g_f[g * 128 + c] = val;
    dout[g * 128 + c] = val;
}

// ---------------- MLP layer (round-1 exact) --------------------------------
__global__ __launch_bounds__(256) void k_fc(const float* __restrict__ in,
                                            const float* __restrict__ W,
                                            const float* __restrict__ b,
                                            float* __restrict__ out,
                                            int K, int C, int relu) {
    __shared__ float s_in[1024];
    int g = blockIdx.x;
    for (int k = threadIdx.x; k < K; k += blockDim.x) s_in[k] = in[g * K + k];
    __syncthreads();
    int c = blockIdx.y * blockDim.x + threadIdx.x;
    if (c < C) {
        float acc = b[c];
        for (int k = 0; k < K; k++) acc = fmaf(s_in[k], W[(size_t)k * C + c], acc);
        if (relu) acc = fmaxf(acc, 0.f);
        out[g * C + c] = acc;
    }
}

extern "C" void kernel_launch(void* const* d_in, const int* in_sizes, int n_in,
                              void* d_out, int out_size) {
    const float* x     = (const float*)d_in[0];
    const int*   ei    = (const int*)d_in[1];
    const int*   batch = (const int*)d_in[2];
    const float* c1w = (const float*)d_in[3];
    const float* c1b = (const float*)d_in[4];
    const float* c2w = (const float*)d_in[5];
    const float* c2b = (const float*)d_in[6];
    const float* c3w = (const float*)d_in[7];
    const float* c3b = (const float*)d_in[8];
    const float* f1w = (const float*)d_in[9];
    const float* f1b = (const float*)d_in[10];
    const float* f2w = (const float*)d_in[11];
    const float* f2b = (const float*)d_in[12];
    const float* f3w = (const float*)d_in[13];
    const float* f3b = (const float*)d_in[14];
    const float* f4w = (const float*)d_in[15];
    const float* f4b = (const float*)d_in[16];
    const float* f5w = (const float*)d_in[17];
    const float* f5b = (const float*)d_in[18];
    float* dout = (float*)d_out;

    float *p_z, *p_h, *p_f, *p_t1, *p_t2, *p_t3, *p_t4;
    int* p_degi;
    cudaGetSymbolAddress((void**)&p_z,  g_z);
    cudaGetSymbolAddress((void**)&p_h,  g_h);
    cudaGetSymbolAddress((void**)&p_f,  g_f);
    cudaGetSymbolAddress((void**)&p_t1, g_t1);
    cudaGetSymbolAddress((void**)&p_t2, g_t2);
    cudaGetSymbolAddress((void**)&p_t3, g_t3);
    cudaGetSymbolAddress((void**)&p_t4, g_t4);
    cudaGetSymbolAddress((void**)&p_degi, g_degi);

    static cudaStream_t s2 = 0;
    static cudaEvent_t evA = 0, evB = 0;
    if (!s2) {
        cudaStreamCreateWithFlags(&s2, cudaStreamNonBlocking);
        cudaEventCreateWithFlags(&evA, cudaEventDisableTiming);
        cudaEventCreateWithFlags(&evB, cudaEventDisableTiming);
    }

    int nb = (NN + 1023) / 1024;
    int gemm_blocks = (NN + 63) / 64;
    int agg_blocks  = (NN * 32 + 255) / 256;

    // fork: CSR build on s2, raw conv1 GEMM (no dinv dependency) on main
    cudaEventRecord(evA, 0);
    cudaStreamWaitEvent(s2, evA, 0);
    cudaMemsetAsync(p_degi, 0, NN * sizeof(int), s2);
    k_count<<<(EE + 255) / 256, 256, 0, s2>>>(ei);
    k_scan1<<<nb, 1024, 0, s2>>>();
    k_scan3<<<nb, 1024, 0, s2>>>(nb);
    k_fill<<<(EE + 255) / 256, 256, 0, s2>>>(ei);
    cudaEventRecord(evB, s2);

    k_gemm_raw<<<gemm_blocks, 256>>>(x, c1w, p_z, NN);   // overlaps CSR build

    cudaStreamWaitEvent(0, evB, 0);                      // join before agg1

    // agg1 consumes raw z -> applies dinv to self and neighbors
    k_agg<<<agg_blocks, 256>>>(p_z, c1b, p_h, 1, 1);
    // conv2/conv3: dinv ready -> scaled GEMM + round-1 agg
    k_gemm<<<gemm_blocks, 256>>>(p_h, c2w, p_z, NN);
    k_agg<<<agg_blocks, 256>>>(p_z, c2b, p_h, 1, 0);
    k_gemm<<<gemm_blocks, 256>>>(p_h, c3w, p_z, NN);
    k_agg<<<agg_blocks, 256>>>(p_z, c3b, p_h, 0, 0);

    k_pool<<<GG, 128>>>(p_h, batch, dout);

    k_fc<<<dim3(GG, (1024 + 255) / 256), 256>>>(p_f,  f1w, f1b, p_t1, 128,  1024, 1);
    k_fc<<<dim3(GG, (512  + 255) / 256), 256>>>(p_t1, f2w, f2b, p_t2, 1024, 512,  1);
    k_fc<<<dim3(GG, (256  + 255) / 256), 256>>>(p_t2, f3w, f3b, p_t3, 512,  256,  1);
    k_fc<<<dim3(GG, (128  + 255) / 256), 256>>>(p_t3, f4w, f4b, p_t4, 256,  128,  1);
    k_fc<<<dim3(GG, 1), 256>>>(p_t4, f5w, f5b, dout + GG * HD, 128, 10, 0);
}

// round 8
// speedup vs baseline: 2.4581x; 1.2176x over previous
#include <cuda_runtime.h>
#include <math.h>
#include <stdint.h>

#define NN 50000
#define EE 800000
#define HD 128
#define GG 64

// ---------------- scratch (device globals: allocation-free) ----------------
__device__ float g_z[NN * HD];
__device__ float g_h[NN * HD];
__device__ float g_dinv[NN];
__device__ int   g_degi[NN];
__device__ int   g_rowptr[NN + 1];
__device__ int   g_cursor[NN];
__device__ int   g_col[EE];
__device__ int   g_bsum[64];
__device__ float g_f[GG * HD];
__device__ float g_t1[GG * 1024];
__device__ float g_t2[GG * 512];
__device__ float g_t3[GG * 256];
__device__ float g_t4[GG * HD];
__device__ float g_wT[3 * HD * HD];   // W^T, tf32-rounded, per conv layer

// ---------------- helpers ----------------
__device__ __forceinline__ float tf32_rna(float x) {
    uint32_t r; asm("cvt.rna.tf32.f32 %0, %1;" : "=r"(r) : "f"(x));
    return __uint_as_float(r);
}
__device__ __forceinline__ void mma_tf32(float* c, const uint32_t* a, const uint32_t* b) {
    asm volatile(
        "mma.sync.aligned.m16n8k8.row.col.f32.tf32.tf32.f32 "
        "{%0,%1,%2,%3}, {%4,%5,%6,%7}, {%8,%9}, {%0,%1,%2,%3};"
        : "+f"(c[0]), "+f"(c[1]), "+f"(c[2]), "+f"(c[3])
        : "r"(a[0]), "r"(a[1]), "r"(a[2]), "r"(a[3]), "r"(b[0]), "r"(b[1]));
}

// ---------------- CSR build ----------------
__global__ void k_count(const int* __restrict__ ei) {
    int e = blockIdx.x * blockDim.x + threadIdx.x;
    if (e < EE) atomicAdd(&g_degi[ei[EE + e]], 1);
}
__global__ void k_scan1() {
    __shared__ int s[1024];
    int t = threadIdx.x;
    int i = blockIdx.x * 1024 + t;
    int v = (i < NN) ? g_degi[i] : 0;
    s[t] = v;
    __syncthreads();
    for (int off = 1; off < 1024; off <<= 1) {
        int x = (t >= off) ? s[t - off] : 0;
        __syncthreads();
        s[t] += x;
        __syncthreads();
    }
    if (i < NN) g_rowptr[i] = s[t] - v;
    if (t == 1023) g_bsum[blockIdx.x] = s[1023];
}
__global__ void k_scan3(int nb) {
    __shared__ int sb[64];
    __shared__ int off_s;
    int t = threadIdx.x;
    if (t < nb) sb[t] = g_bsum[t];
    __syncthreads();
    if (t == 0) {
        int s = 0;
        for (int i = 0; i < blockIdx.x; i++) s += sb[i];
        off_s = s;
    }
    __syncthreads();
    int i = blockIdx.x * 1024 + t;
    if (i < NN) {
        int rp = g_rowptr[i] + off_s;
        g_rowptr[i] = rp;
        g_cursor[i] = rp;
        g_dinv[i]   = rsqrtf((float)(g_degi[i] + 1));
    }
    if (i == 0) g_rowptr[NN] = EE;
}
__global__ void k_fill(const int* __restrict__ ei) {
    int e = blockIdx.x * blockDim.x + threadIdx.x;
    if (e < EE) {
        int src = ei[e];
        int dst = ei[EE + e];
        int p = atomicAdd(&g_cursor[dst], 1);
        g_col[p] = src;
    }
}

// ---------------- weight prep: W[k][n] -> WT[n][k], tf32-rounded -----------
__global__ __launch_bounds__(256) void k_prep(const float* __restrict__ w1,
                                              const float* __restrict__ w2,
                                              const float* __restrict__ w3) {
    int layer = blockIdx.x >> 3;           // 0..2
    int part  = blockIdx.x & 7;            // 0..7
    const float* W = (layer == 0) ? w1 : ((layer == 1) ? w2 : w3);
    float* o = g_wT + layer * (HD * HD);
    for (int i = 0; i < 8; i++) {
        int idx = part * 2048 + i * 256 + threadIdx.x;   // 0..16383
        int k = idx >> 7;
        int n = idx & 127;
        o[n * HD + k] = tf32_rna(W[idx]);
    }
}

// ---------------- single-pass tf32 mma GEMM: C = [dinv[r]*] (A @ W) --------
// A: [M,128] fp32 (rounded to tf32 in staging). WT: [128n][128k] tf32.
// Block 128x128, 8 warps (4m x 2n), warp tile 32x64, BK=32, m16n8k8.
#define APITCH 36
#define SM_AS 0
#define SM_BS (128 * APITCH)
#define SM_GEMM_FLOATS (2 * 128 * APITCH)

__global__ __launch_bounds__(256, 2) void k_gemm_mma(const float* __restrict__ A,
                                                     const float* __restrict__ WT,
                                                     float* __restrict__ C,
                                                     int M, int scale) {
    extern __shared__ float sm[];
    int tid  = threadIdx.x;
    int wid  = tid >> 5;
    int lane = tid & 31;
    int g    = lane >> 2;
    int tig  = lane & 3;
    int wm   = wid & 3;
    int wn   = wid >> 2;
    int base = blockIdx.x * 128;

    float c[2][8][4];
    #pragma unroll
    for (int f = 0; f < 2; f++)
        #pragma unroll
        for (int j = 0; j < 8; j++)
            #pragma unroll
            for (int q = 0; q < 4; q++) c[f][j][q] = 0.f;

    for (int kc = 0; kc < 4; kc++) {
        int k0 = kc * 32;
        // stage A chunk [128 x 32], tf32-round on the fly
        #pragma unroll
        for (int i = 0; i < 4; i++) {
            int idx = i * 256 + tid;           // 0..1023 float4s
            int row = idx >> 3;
            int c4  = (idx & 7) * 4;
            float4 a = make_float4(0.f, 0.f, 0.f, 0.f);
            int gr = base + row;
            if (gr < M) a = *(const float4*)(A + (size_t)gr * HD + k0 + c4);
            a.x = tf32_rna(a.x); a.y = tf32_rna(a.y);
            a.z = tf32_rna(a.z); a.w = tf32_rna(a.w);
            *(float4*)(sm + SM_AS + row * APITCH + c4) = a;
        }
        // stage B chunk: WT[n][k0..k0+31] (pre-rounded), plain copy
        #pragma unroll
        for (int i = 0; i < 4; i++) {
            int idx = i * 256 + tid;
            int n  = idx >> 3;
            int c4 = (idx & 7) * 4;
            *(float4*)(sm + SM_BS + n * APITCH + c4) =
                *(const float4*)(WT + (size_t)n * HD + k0 + c4);
        }
        __syncthreads();

        #pragma unroll
        for (int ks = 0; ks < 4; ks++) {
            int k = ks * 8;
            uint32_t af[2][4];
            #pragma unroll
            for (int f = 0; f < 2; f++) {
                int r0 = (wm * 32 + f * 16 + g) * APITCH + k + tig;
                int r1 = (wm * 32 + f * 16 + 8 + g) * APITCH + k + tig;
                af[f][0] = __float_as_uint(sm[SM_AS + r0]);
                af[f][1] = __float_as_uint(sm[SM_AS + r1]);
                af[f][2] = __float_as_uint(sm[SM_AS + r0 + 4]);
                af[f][3] = __float_as_uint(sm[SM_AS + r1 + 4]);
            }
            #pragma unroll
            for (int j = 0; j < 8; j++) {
                int nb = (wn * 64 + j * 8 + g) * APITCH + k + tig;
                uint32_t bf[2];
                bf[0] = __float_as_uint(sm[SM_BS + nb]);
                bf[1] = __float_as_uint(sm[SM_BS + nb + 4]);
                mma_tf32(c[0][j], af[0], bf);
                mma_tf32(c[1][j], af[1], bf);
            }
        }
        __syncthreads();
    }

    // epilogue
    #pragma unroll
    for (int f = 0; f < 2; f++) {
        int r0 = base + wm * 32 + f * 16 + g;
        int r1 = r0 + 8;
        float d0 = 1.f, d1 = 1.f;
        if (scale) {
            if (r0 < M) d0 = g_dinv[r0];
            if (r1 < M) d1 = g_dinv[r1];
        }
        #pragma unroll
        for (int j = 0; j < 8; j++) {
            int col = wn * 64 + j * 8 + 2 * tig;
            if (r0 < M)
                *(float2*)(C + (size_t)r0 * HD + col) =
                    make_float2(c[f][j][0] * d0, c[f][j][1] * d0);
            if (r1 < M)
                *(float2*)(C + (size_t)r1 * HD + col) =
                    make_float2(c[f][j][2] * d1, c[f][j][3] * d1);
        }
    }
}

// ---------------- aggregation (round-1 exact), optional self-scale ---------
__global__ __launch_bounds__(256) void k_agg(const float* __restrict__ z,
                                             const float* __restrict__ bias,
                                             float* __restrict__ out,
                                             int relu, int scale_self) {
    int wid  = (blockIdx.x * blockDim.x + threadIdx.x) >> 5;
    int lane = threadIdx.x & 31;
    if (wid >= NN) return;
    const float4* z4 = (const float4*)z;
    float dv = g_dinv[wid];
    float4 acc = z4[(size_t)wid * 32 + lane];
    if (scale_self) { acc.x *= dv; acc.y *= dv; acc.z *= dv; acc.w *= dv; }
    int beg = g_rowptr[wid];
    int end = g_rowptr[wid + 1];
    int j = beg;
    if (scale_self) {
        for (; j + 1 < end; j += 2) {
            int u0 = g_col[j], u1 = g_col[j + 1];
            float d0 = g_dinv[u0], d1 = g_dinv[u1];
            float4 a = z4[(size_t)u0 * 32 + lane];
            float4 b = z4[(size_t)u1 * 32 + lane];
            acc.x = fmaf(d0, a.x, acc.x); acc.y = fmaf(d0, a.y, acc.y);
            acc.z = fmaf(d0, a.z, acc.z); acc.w = fmaf(d0, a.w, acc.w);
            acc.x = fmaf(d1, b.x, acc.x); acc.y = fmaf(d1, b.y, acc.y);
            acc.z = fmaf(d1, b.z, acc.z); acc.w = fmaf(d1, b.w, acc.w);
        }
        for (; j < end; j++) {
            int u = g_col[j];
            float du = g_dinv[u];
            float4 a = z4[(size_t)u * 32 + lane];
            acc.x = fmaf(du, a.x, acc.x); acc.y = fmaf(du, a.y, acc.y);
            acc.z = fmaf(du, a.z, acc.z); acc.w = fmaf(du, a.w, acc.w);
        }
    } else {
        for (; j + 3 < end; j += 4) {
            int u0 = g_col[j], u1 = g_col[j + 1], u2 = g_col[j + 2], u3 = g_col[j + 3];
            float4 a = z4[(size_t)u0 * 32 + lane];
            float4 b = z4[(size_t)u1 * 32 + lane];
            float4 c = z4[(size_t)u2 * 32 + lane];
            float4 d = z4[(size_t)u3 * 32 + lane];
            acc.x += (a.x + b.x) + (c.x + d.x);
            acc.y += (a.y + b.y) + (c.y + d.y);
            acc.z += (a.z + b.z) + (c.z + d.z);
            acc.w += (a.w + b.w) + (c.w + d.w);
        }
        for (; j < end; j++) {
            float4 a = z4[(size_t)g_col[j] * 32 + lane];
            acc.x += a.x; acc.y += a.y; acc.z += a.z; acc.w += a.w;
        }
    }
    float4 bb = ((const float4*)bias)[lane];
    float4 r;
    r.x = fmaf(acc.x, dv, bb.x);
    r.y = fmaf(acc.y, dv, bb.y);
    r.z = fmaf(acc.z, dv, bb.z);
    r.w = fmaf(acc.w, dv, bb.w);
    if (relu) {
        r.x = fmaxf(r.x, 0.f); r.y = fmaxf(r.y, 0.f);
        r.z = fmaxf(r.z, 0.f); r.w = fmaxf(r.w, 0.f);
    }
    ((float4*)out)[(size_t)wid * 32 + lane] = r;
}

// ---------------- mean pool per graph ----------------
__global__ __launch_bounds__(128) void k_pool(const float* __restrict__ h,
                                              const int* __restrict__ batch,
                                              float* __restrict__ dout) {
    int g = blockIdx.x;
    int c = threadIdx.x;
    int lo = 0, hi = NN;
    while (lo < hi) { int m = (lo + hi) >> 1; if (batch[m] < g) lo = m + 1; else hi = m; }
    int start = lo;
    lo = 0; hi = NN;
    while (lo < hi) { int m = (lo + hi) >> 1; if (batch[m] < g + 1) lo = m + 1; else hi = m; }
    int end = lo;
    float s = 0.f;
    for (int v = start; v < end; v++) s += h[(size_t)v * 128 + c];
    float cnt = (float)(end - start);
    float val = s / fmaxf(cnt, 1.0f);
    g_f[g * 128 + c] = val;
    dout[g * 128 + c] = val;
}

// ---------------- MLP layer (round-1 exact) --------------------------------
__global__ __launch_bounds__(256) void k_fc(const float* __restrict__ in,
                                            const float* __restrict__ W,
                                            const float* __restrict__ b,
                                            float* __restrict__ out,
                                            int K, int C, int relu) {
    __shared__ float s_in[1024];
    int g = blockIdx.x;
    for (int k = threadIdx.x; k < K; k += blockDim.x) s_in[k] = in[g * K + k];
    __syncthreads();
    int c = blockIdx.y * blockDim.x + threadIdx.x;
    if (c < C) {
        float acc = b[c];
        for (int k = 0; k < K; k++) acc = fmaf(s_in[k], W[(size_t)k * C + c], acc);
        if (relu) acc = fmaxf(acc, 0.f);
        out[g * C + c] = acc;
    }
}

extern "C" void kernel_launch(void* const* d_in, const int* in_sizes, int n_in,
                              void* d_out, int out_size) {
    const float* x     = (const float*)d_in[0];
    const int*   ei    = (const int*)d_in[1];
    const int*   batch = (const int*)d_in[2];
    const float* c1w = (const float*)d_in[3];
    const float* c1b = (const float*)d_in[4];
    const float* c2w = (const float*)d_in[5];
    const float* c2b = (const float*)d_in[6];
    const float* c3w = (const float*)d_in[7];
    const float* c3b = (const float*)d_in[8];
    const float* f1w = (const float*)d_in[9];
    const float* f1b = (const float*)d_in[10];
    const float* f2w = (const float*)d_in[11];
    const float* f2b = (const float*)d_in[12];
    const float* f3w = (const float*)d_in[13];
    const float* f3b = (const float*)d_in[14];
    const float* f4w = (const float*)d_in[15];
    const float* f4b = (const float*)d_in[16];
    const float* f5w = (const float*)d_in[17];
    const float* f5b = (const float*)d_in[18];
    float* dout = (float*)d_out;

    float *p_z, *p_h, *p_f, *p_t1, *p_t2, *p_t3, *p_t4, *p_wT;
    int* p_degi;
    cudaGetSymbolAddress((void**)&p_z,  g_z);
    cudaGetSymbolAddress((void**)&p_h,  g_h);
    cudaGetSymbolAddress((void**)&p_f,  g_f);
    cudaGetSymbolAddress((void**)&p_t1, g_t1);
    cudaGetSymbolAddress((void**)&p_t2, g_t2);
    cudaGetSymbolAddress((void**)&p_t3, g_t3);
    cudaGetSymbolAddress((void**)&p_t4, g_t4);
    cudaGetSymbolAddress((void**)&p_wT, g_wT);
    cudaGetSymbolAddress((void**)&p_degi, g_degi);

    static cudaStream_t s2 = 0;
    static cudaEvent_t evA = 0, evB = 0;
    static int init_done = 0;
    if (!init_done) {
        cudaStreamCreateWithFlags(&s2, cudaStreamNonBlocking);
        cudaEventCreateWithFlags(&evA, cudaEventDisableTiming);
        cudaEventCreateWithFlags(&evB, cudaEventDisableTiming);
        cudaFuncSetAttribute(k_gemm_mma, cudaFuncAttributeMaxDynamicSharedMemorySize,
                             SM_GEMM_FLOATS * sizeof(float));
        init_done = 1;
    }

    int nb = (NN + 1023) / 1024;
    int gemm_blocks = (NN + 127) / 128;
    int agg_blocks  = (NN * 32 + 255) / 256;
    size_t gsm = SM_GEMM_FLOATS * sizeof(float);

    // fork: CSR build on s2; weight prep + raw conv1 GEMM on main
    cudaEventRecord(evA, 0);
    cudaStreamWaitEvent(s2, evA, 0);
    cudaMemsetAsync(p_degi, 0, NN * sizeof(int), s2);
    k_count<<<(EE + 255) / 256, 256, 0, s2>>>(ei);
    k_scan1<<<nb, 1024, 0, s2>>>();
    k_scan3<<<nb, 1024, 0, s2>>>(nb);
    k_fill<<<(EE + 255) / 256, 256, 0, s2>>>(ei);
    cudaEventRecord(evB, s2);

    k_prep<<<24, 256>>>(c1w, c2w, c3w);
    k_gemm_mma<<<gemm_blocks, 256, gsm>>>(x, p_wT, p_z, NN, 0);  // raw, overlaps CSR

    cudaStreamWaitEvent(0, evB, 0);                              // join before agg1

    k_agg<<<agg_blocks, 256>>>(p_z, c1b, p_h, 1, 1);
    k_gemm_mma<<<gemm_blocks, 256, gsm>>>(p_h, p_wT + HD * HD, p_z, NN, 1);
    k_agg<<<agg_blocks, 256>>>(p_z, c2b, p_h, 1, 0);
    k_gemm_mma<<<gemm_blocks, 256, gsm>>>(p_h, p_wT + 2 * HD * HD, p_z, NN, 1);
    k_agg<<<agg_blocks, 256>>>(p_z, c3b, p_h, 0, 0);

    k_pool<<<GG, 128>>>(p_h, batch, dout);

    k_fc<<<dim3(GG, (1024 + 255) / 256), 256>>>(p_f,  f1w, f1b, p_t1, 128,  1024, 1);
    k_fc<<<dim3(GG, (512  + 255) / 256), 256>>>(p_t1, f2w, f2b, p_t2, 1024, 512,  1);
    k_fc<<<dim3(GG, (256  + 255) / 256), 256>>>(p_t2, f3w, f3b, p_t3, 512,  256,  1);
    k_fc<<<dim3(GG, (128  + 255) / 256), 256>>>(p_t3, f4w, f4b, p_t4, 256,  128,  1);
    k_fc<<<dim3(GG, 1), 256>>>(p_t4, f5w, f5b, dout + GG * HD, 128, 10, 0);
}